// round 6
// baseline (speedup 1.0000x reference)
#include <cuda_runtime.h>

// HolographicLayer: eta = dot(R[p], ccorr_half(E[s], E[o]))
//   ccorr_half(a,b)[k] = sum_i a[k+i-100] * b[i], zero-padded, d=201
// With padded smem sp (sp[100+j] = a[j], zeros elsewhere):
//   eta = sum_k rv[k] * sum_i sp[k+i] * bv[i]
// Single block. Thread t owns a 4-k x 44-i register tile:
//   tc = t/51 (i-chunk), tk = t%51 (k-group of 4).
// Sliding window: s0 of iteration j+4 == s1 of iteration j, so only ONE
// new sp float4 is loaded per iteration (halves smem crossbar traffic).
// rv is loaded per-thread from global, issued early to hide latency.

#define D      201
#define PAD    100
#define NT     256
#define SPLEN  480    // max sp index touched: 200+220+47 = 467
#define BVLEN  264    // max bv index touched: 220+43   = 263

__global__ void __launch_bounds__(NT, 1)
holo_kernel(const int* __restrict__ x,
            const float* __restrict__ E,
            const float* __restrict__ R,
            float* __restrict__ out) {
    __shared__ __align__(16) float sp[SPLEN];
    __shared__ __align__(16) float bv[BVLEN];
    __shared__ __align__(16) float wsum[NT / 32];

    const int t = threadIdx.x;

    // x is [32,3] row-major; row 0 = (s, o, p)
    const int s = x[0], o = x[1], p = x[2];
    const float* __restrict__ Es = E + (long long)s * D;
    const float* __restrict__ Eo = E + (long long)o * D;
    const float* __restrict__ Rp = R + (long long)p * D;

    // Tile coordinates: 51 k-groups x 5 i-chunks = 255 threads; the one
    // extra thread lands in chunk 5 (i in [220,264)) where bv == 0.
    const int tc = t / 51;            // i-chunk: 0..5
    const int tk = t - tc * 51;       // k-group: 0..50
    const int k0 = tk * 4;            // multiple of 4 (16B aligned)
    const int ci = tc * 44;           // multiple of 4

    // Issue per-thread R gathers early; consumed after the compute loop,
    // so their latency hides under fill + barrier + FMAs. Guarded: k0+c
    // can reach 203 > 200 (OOB on the last R row).
    const float r0 = Rp[k0];
    const float r1 = (k0 + 1 < D) ? Rp[k0 + 1] : 0.0f;
    const float r2 = (k0 + 2 < D) ? Rp[k0 + 2] : 0.0f;
    const float r3 = (k0 + 3 < D) ? Rp[k0 + 3] : 0.0f;

    // Zero-padded fills trimmed to actual extents, one sync.
    sp[t] = (t >= PAD && t < PAD + D) ? Es[t - PAD] : 0.0f;
    {
        const int m = t + NT;
        if (m < SPLEN) sp[m] = (m < PAD + D) ? Es[m - PAD] : 0.0f;
    }
    bv[t] = (t < D) ? Eo[t] : 0.0f;
    if (t < BVLEN - NT) bv[t + NT] = 0.0f;
    __syncthreads();

    // 4 accumulators break the FMA chain; sliding-window sp loads.
    float a0 = 0.0f, a1 = 0.0f, a2 = 0.0f, a3 = 0.0f;
    float4 s0 = *reinterpret_cast<const float4*>(&sp[k0 + ci]);
    #pragma unroll
    for (int j = 0; j < 44; j += 4) {
        const float4 s1 = *reinterpret_cast<const float4*>(&sp[k0 + ci + j + 4]);
        const float4 b4 = *reinterpret_cast<const float4*>(&bv[ci + j]);

        a0 = fmaf(s0.x, b4.x, a0); a0 = fmaf(s0.y, b4.y, a0);
        a0 = fmaf(s0.z, b4.z, a0); a0 = fmaf(s0.w, b4.w, a0);

        a1 = fmaf(s0.y, b4.x, a1); a1 = fmaf(s0.z, b4.y, a1);
        a1 = fmaf(s0.w, b4.z, a1); a1 = fmaf(s1.x, b4.w, a1);

        a2 = fmaf(s0.z, b4.x, a2); a2 = fmaf(s0.w, b4.y, a2);
        a2 = fmaf(s1.x, b4.z, a2); a2 = fmaf(s1.y, b4.w, a2);

        a3 = fmaf(s0.w, b4.x, a3); a3 = fmaf(s1.x, b4.y, a3);
        a3 = fmaf(s1.y, b4.z, a3); a3 = fmaf(s1.z, b4.w, a3);

        s0 = s1;
    }

    // Fold in rv (spare chunk's accumulators are all zero).
    float v = r0 * a0;
    v = fmaf(r1, a1, v);
    v = fmaf(r2, a2, v);
    v = fmaf(r3, a3, v);

    // Warp reduce, then thread 0 sums the 8 warp partials serially
    // (2x LDS.128 + 7 adds beats a second shfl stage at 26 cyc/shfl).
    #pragma unroll
    for (int off = 16; off > 0; off >>= 1)
        v += __shfl_down_sync(0xFFFFFFFFu, v, off);
    if ((t & 31) == 0) wsum[t >> 5] = v;
    __syncthreads();

    if (t == 0) {
        const float4 w0 = *reinterpret_cast<const float4*>(&wsum[0]);
        const float4 w1 = *reinterpret_cast<const float4*>(&wsum[4]);
        out[0] = ((w0.x + w0.y) + (w0.z + w0.w))
               + ((w1.x + w1.y) + (w1.z + w1.w));
    }
}

extern "C" void kernel_launch(void* const* d_in, const int* in_sizes, int n_in,
                              void* d_out, int out_size) {
    const int*   x = (const int*)d_in[0];
    const float* E = (const float*)d_in[1];
    const float* R = (const float*)d_in[2];
    float* out = (float*)d_out;
    holo_kernel<<<1, NT>>>(x, E, R, out);
}

// round 9
// speedup vs baseline: 1.0048x; 1.0048x over previous
#include <cuda_runtime.h>

// HolographicLayer: eta = dot(R[p], ccorr_half(E[s], E[o]))
//   ccorr_half(a,b)[k] = sum_i a[k+i-100] * b[i], zero-padded, d=201
// With padded smem sp (sp[100+j] = a[j], zeros elsewhere):
//   eta = sum_k rv[k] * sum_i sp[k+i] * bv[i]
// Single block. Thread t owns a 4-k x 44-i register tile.
// Inner sum vectorized with Blackwell fma.rn.f32x2 (FFMA2): each
// accumulator holds (even-i partial, odd-i partial) for one k; packs for
// the shifted sp pairs ride the alu pipe and dual-issue with the fma pipe.
// Two packs per iteration slide forward (s1's xy/yz become s0's).

#define D      201
#define PAD    100
#define NT     256
#define SPLEN  480    // max sp index touched: 200+220+46 = 466
#define BVLEN  264    // max bv index touched: 220+43    = 263

#define PACKF2(dst, lo, hi) \
    asm("mov.b64 %0, {%1, %2};" : "=l"(dst) : "f"(lo), "f"(hi))
#define FMAF2(d, a, b, c) \
    asm("fma.rn.f32x2 %0, %1, %2, %3;" : "=l"(d) : "l"(a), "l"(b), "l"(c))
#define UNPACKF2(lo, hi, src) \
    asm("mov.b64 {%0, %1}, %2;" : "=f"(lo), "=f"(hi) : "l"(src))

__global__ void __launch_bounds__(NT, 1)
holo_kernel(const int* __restrict__ x,
            const float* __restrict__ E,
            const float* __restrict__ R,
            float* __restrict__ out) {
    __shared__ __align__(16) float sp[SPLEN];
    __shared__ __align__(16) float bv[BVLEN];
    __shared__ __align__(16) float wsum[NT / 32];

    const int t = threadIdx.x;

    // x is [32,3] row-major; row 0 = (s, o, p)
    const int s = x[0], o = x[1], p = x[2];
    const float* __restrict__ Es = E + (long long)s * D;
    const float* __restrict__ Eo = E + (long long)o * D;
    const float* __restrict__ Rp = R + (long long)p * D;

    // 51 k-groups x 5 i-chunks = 255 threads; the spare thread lands in
    // chunk 5 (i in [220,264)) where bv == 0.
    const int tc = t / 51;            // i-chunk: 0..5
    const int tk = t - tc * 51;       // k-group: 0..50
    const int k0 = tk * 4;            // multiple of 4 (16B aligned)
    const int ci = tc * 44;           // multiple of 4

    // Early per-thread R gathers; consumed after the compute loop.
    // Guarded: k0+c can reach 203 > 200.
    const float r0 = Rp[k0];
    const float r1 = (k0 + 1 < D) ? Rp[k0 + 1] : 0.0f;
    const float r2 = (k0 + 2 < D) ? Rp[k0 + 2] : 0.0f;
    const float r3 = (k0 + 3 < D) ? Rp[k0 + 3] : 0.0f;

    // Zero-padded fills trimmed to actual extents, one sync.
    sp[t] = (t >= PAD && t < PAD + D) ? Es[t - PAD] : 0.0f;
    {
        const int m = t + NT;
        if (m < SPLEN) sp[m] = (m < PAD + D) ? Es[m - PAD] : 0.0f;
    }
    bv[t] = (t < D) ? Eo[t] : 0.0f;
    if (t < BVLEN - NT) bv[t + NT] = 0.0f;
    __syncthreads();

    // acc_c holds (even-i, odd-i) partials for k = k0+c as packed f32x2.
    unsigned long long acc0 = 0ull, acc1 = 0ull, acc2 = 0ull, acc3 = 0ull;

    const int idx0 = k0 + ci;
    float4 s0 = *reinterpret_cast<const float4*>(&sp[idx0]);
    unsigned long long pxy, pyz;
    PACKF2(pxy, s0.x, s0.y);
    PACKF2(pyz, s0.y, s0.z);

    #pragma unroll
    for (int j = 0; j < 44; j += 4) {
        const float4 s1 = *reinterpret_cast<const float4*>(&sp[idx0 + j + 4]);
        const float4 b4 = *reinterpret_cast<const float4*>(&bv[ci + j]);

        unsigned long long pzw, pwx, pxy1, pyz1, b01, b23;
        PACKF2(pzw,  s0.z, s0.w);
        PACKF2(pwx,  s0.w, s1.x);
        PACKF2(pxy1, s1.x, s1.y);
        PACKF2(pyz1, s1.y, s1.z);
        PACKF2(b01,  b4.x, b4.y);
        PACKF2(b23,  b4.z, b4.w);

        // i = j, j+1 (pair lanes):
        FMAF2(acc0, pxy, b01, acc0);   // k0:   (sp[idx+0], sp[idx+1])
        FMAF2(acc1, pyz, b01, acc1);   // k0+1: (sp[idx+1], sp[idx+2])
        FMAF2(acc2, pzw, b01, acc2);   // k0+2: (sp[idx+2], sp[idx+3])
        FMAF2(acc3, pwx, b01, acc3);   // k0+3: (sp[idx+3], sp[idx+4])
        // i = j+2, j+3:
        FMAF2(acc0, pzw,  b23, acc0);  // k0:   (sp[idx+2], sp[idx+3])
        FMAF2(acc1, pwx,  b23, acc1);  // k0+1: (sp[idx+3], sp[idx+4])
        FMAF2(acc2, pxy1, b23, acc2);  // k0+2: (sp[idx+4], sp[idx+5])
        FMAF2(acc3, pyz1, b23, acc3);  // k0+3: (sp[idx+5], sp[idx+6])

        s0 = s1;
        pxy = pxy1;
        pyz = pyz1;
    }

    // Collapse packed lanes and fold in rv.
    float e0, o0, e1, o1, e2, o2, e3, o3;
    UNPACKF2(e0, o0, acc0);
    UNPACKF2(e1, o1, acc1);
    UNPACKF2(e2, o2, acc2);
    UNPACKF2(e3, o3, acc3);
    float v = r0 * (e0 + o0);
    v = fmaf(r1, e1 + o1, v);
    v = fmaf(r2, e2 + o2, v);
    v = fmaf(r3, e3 + o3, v);

    // Warp reduce, then thread 0 sums the 8 warp partials serially.
    #pragma unroll
    for (int off = 16; off > 0; off >>= 1)
        v += __shfl_down_sync(0xFFFFFFFFu, v, off);
    if ((t & 31) == 0) wsum[t >> 5] = v;
    __syncthreads();

    if (t == 0) {
        const float4 w0 = *reinterpret_cast<const float4*>(&wsum[0]);
        const float4 w1 = *reinterpret_cast<const float4*>(&wsum[4]);
        out[0] = ((w0.x + w0.y) + (w0.z + w0.w))
               + ((w1.x + w1.y) + (w1.z + w1.w));
    }
}

extern "C" void kernel_launch(void* const* d_in, const int* in_sizes, int n_in,
                              void* d_out, int out_size) {
    const int*   x = (const int*)d_in[0];
    const float* E = (const float*)d_in[1];
    const float* R = (const float*)d_in[2];
    float* out = (float*)d_out;
    holo_kernel<<<1, NT>>>(x, E, R, out);
}